// round 13
// baseline (speedup 1.0000x reference)
#include <cuda_runtime.h>
#include <cuda_bf16.h>
#include <math.h>
#include <stdint.h>

#define Bn 128
#define Tn 256
#define Ln 64
#define Sn 25
#define Hn 128
#define NT 512

#define ZF_SZ  52428800   // 25*128*256*64
#define M_SZ   2097152    // 128*256*64

#define ZW  36    // words per z bf16 row
#define ZFW 68    // words per zf32 row
#define PWD 36    // P row stride (per l), words
#define PBLK 2304 // 64*PWD per warp-k-block

// smem word offsets
#define OFF_P   0
#define OFF_ZF  18432
#define OFF_ZH  20608
#define OFF_ZL  21760
#define OFF_R1  22912
#define OFF_R2  23456
#define SM_WORDS 24000
#define SMEM_BYTES (SM_WORDS*4)

__device__ __forceinline__ float tanh_fast(float x) {
    float y;
    asm("tanh.approx.f32 %0, %1;" : "=f"(y) : "f"(x));
    return y;
}
__device__ __forceinline__ uint32_t pack_bf(float a, float b) {
    uint16_t ua = __bfloat16_as_ushort(__float2bfloat16(a));
    uint16_t ub = __bfloat16_as_ushort(__float2bfloat16(b));
    return (uint32_t)ua | ((uint32_t)ub << 16);
}
__device__ __forceinline__ void split2(float a, float b, uint32_t& hi, uint32_t& lo) {
    float ah = __bfloat162float(__float2bfloat16(a));
    float bh = __bfloat162float(__float2bfloat16(b));
    hi = pack_bf(a, b);
    lo = pack_bf(a - ah, b - bh);
}
__device__ __forceinline__ void mma16816(float* d, const uint32_t* a,
                                         uint32_t b0, uint32_t b1) {
    asm volatile(
        "mma.sync.aligned.m16n8k16.row.col.f32.bf16.bf16.f32 "
        "{%0,%1,%2,%3},{%4,%5,%6,%7},{%8,%9},{%0,%1,%2,%3};"
        : "+f"(d[0]), "+f"(d[1]), "+f"(d[2]), "+f"(d[3])
        : "r"(a[0]), "r"(a[1]), "r"(a[2]), "r"(a[3]), "r"(b0), "r"(b1));
}
__device__ __forceinline__ void ldm4(uint32_t addr, uint32_t* r) {
    asm volatile("ldmatrix.sync.aligned.m8n8.x4.shared.b16 {%0,%1,%2,%3}, [%4];"
        : "=r"(r[0]), "=r"(r[1]), "=r"(r[2]), "=r"(r[3]) : "r"(addr));
}
// P index with bank swizzle: conflict-free for both frag-writes and f4-reads
__device__ __forceinline__ int pidx(int wn, int l, int s) {
    return wn*PBLK + l*PWD + ((s + 8*(l & 3)) & 31);
}

__global__ __launch_bounds__(NT, 1)
void nlf_kernel(const float* __restrict__ k_in,
                const float* __restrict__ K_in,
                const float* __restrict__ noise,
                const float* __restrict__ logQ,
                const float* __restrict__ m0,
                const float* __restrict__ logQ0,
                const float* __restrict__ W1,
                const float* __restrict__ b1,
                const float* __restrict__ W2,
                const float* __restrict__ b2,
                float* __restrict__ out)
{
    extern __shared__ float smf[];
    float*    Pf   = smf + OFF_P;
    float*    zf   = smf + OFF_ZF;
    uint32_t* zhiW = (uint32_t*)(smf + OFF_ZH);
    uint32_t* zloW = (uint32_t*)(smf + OFF_ZL);
    float*    sR1  = smf + OFF_R1;   // [8][68]
    float*    sR2  = smf + OFF_R2;

    const int tid  = threadIdx.x;
    const int b    = blockIdx.x;
    const int w    = tid >> 5;
    const int lane = tid & 31;
    const int lq   = tid & 63;

    const int mt = w & 1;        // s-half m-tile
    const int wn = w >> 1;       // 0..7: GEMM1 h-pair / GEMM2 k-block
    const int c  = lane & 3;
    const int hq = lane >> 2;

    // ldmatrix addresses for z
    const int lrow = mt*16 + (lane & 15);
    const int lcw  = (lane >> 4) * 4;
    const uint32_t zhB = (uint32_t)__cvta_generic_to_shared(zhiW) + (lrow*ZW + lcw)*4;
    const uint32_t zlB = (uint32_t)__cvta_generic_to_shared(zloW) + (lrow*ZW + lcw)*4;

    // -------- register weight fragments --------
    uint32_t w1h[2][4][2], w1l[2][4][2];
    #pragma unroll
    for (int j = 0; j < 2; j++) {
        int h = 8*(2*wn + j) + hq;
        #pragma unroll
        for (int ko = 0; ko < 4; ko++) {
            int k0 = 16*ko + 2*c;
            split2(W1[(k0+0)*Hn + h], W1[(k0+1)*Hn + h], w1h[j][ko][0], w1l[j][ko][0]);
            split2(W1[(k0+8)*Hn + h], W1[(k0+9)*Hn + h], w1h[j][ko][1], w1l[j][ko][1]);
        }
    }
    // GEMM2: B-frag per l-tile nj for k-block h in [16wn, 16wn+16)
    uint32_t w2h[8][2], w2l[8][2];
    {
        int kh = 16*wn;
        #pragma unroll
        for (int nj = 0; nj < 8; nj++) {
            int l2 = 8*nj + hq;
            split2(W2[(kh+2*c+0)*Ln + l2], W2[(kh+2*c+1)*Ln + l2], w2h[nj][0], w2l[nj][0]);
            split2(W2[(kh+8+2*c+0)*Ln + l2], W2[(kh+8+2*c+1)*Ln + l2], w2h[nj][1], w2l[nj][1]);
        }
    }
    float b1f[2][2];
    #pragma unroll
    for (int j = 0; j < 2; j++) {
        b1f[j][0] = b1[8*(2*wn + j) + 2*c];
        b1f[j][1] = b1[8*(2*wn + j) + 2*c + 1];
    }
    // stage1 constants
    const int   lS = tid & 63;
    const int   sg = tid >> 6;       // 0..7
    const int   s0 = sg * 4;
    const float b2v = b2[lS];
    const float Qd  = log1pf(expf(logQ[lq]));

    __nv_bfloat16* zh = (__nv_bfloat16*)zhiW;   // row stride 72 bf16
    __nv_bfloat16* zl = (__nv_bfloat16*)zloW;

    // -------- init: zero z bf16 arrays (rows 25..31 stay 0), t=0 filter --------
    for (int i = tid; i < 32*ZW; i += NT) { zhiW[i] = 0; zloW[i] = 0; }
    if (tid < 64) {
        int l = tid;
        float P0 = log1pf(expf(logQ0[l]));
        float J0 = 1.0f / P0;
        float h0 = J0 * m0[l];
        int  go  = (b*Tn + 0)*Ln + l;
        float Kv = K_in[go], kv = k_in[go];
        float Jf = J0 + Kv;
        float Pfv = 1.0f / Jf;
        float mf = Pfv * (h0 + kv);
        out[ZF_SZ + 0*M_SZ + go] = mf;
        out[ZF_SZ + 1*M_SZ + go] = m0[l];
        out[ZF_SZ + 2*M_SZ + go] = Pfv;
        out[ZF_SZ + 3*M_SZ + go] = P0;
        sR1[l] = mf;
        sR2[l] = sqrtf(Pfv);
    }
    __syncthreads();

    // z update for t = 0
    {
        float mf = sR1[lq], spf = sR2[lq];
        #pragma unroll
        for (int i = 0; i < 3; i++) {
            int idx = tid + i*NT, s = idx >> 6;
            float zv = mf + spf * noise[((0*Sn + s)*Bn + b)*Ln + lq];
            out[((s*Bn + b)*Tn + 0)*Ln + lq] = zv;
            zf[s*ZFW + lq] = zv;
            float zvh = __bfloat162float(__float2bfloat16(zv));
            zh[s*72 + lq] = __float2bfloat16(zv);
            zl[s*72 + lq] = __float2bfloat16(zv - zvh);
        }
        if (tid < 64) {
            float zv = mf + spf * noise[((0*Sn + 24)*Bn + b)*Ln + lq];
            out[((24*Bn + b)*Tn + 0)*Ln + lq] = zv;
            zf[24*ZFW + lq] = zv;
            float zvh = __bfloat162float(__float2bfloat16(zv));
            zh[24*72 + lq] = __float2bfloat16(zv);
            zl[24*72 + lq] = __float2bfloat16(zv - zvh);
        }
    }

    for (int t = 1; t < Tn; t++) {
        // -------- prefetch globals --------
        float npf[4];
        #pragma unroll
        for (int i = 0; i < 3; i++) {
            int idx = tid + i*NT;
            npf[i] = noise[((t*Sn + (idx >> 6))*Bn + b)*Ln + lq];
        }
        npf[3] = (tid < 64) ? noise[((t*Sn + 24)*Bn + b)*Ln + lq] : 0.0f;
        const int go = (b*Tn + t)*Ln + lq;
        const float Kv_pf = K_in[go];
        const float kv_pf = k_in[go];

        __syncthreads();   // #1: z ready; prev stage1 done reading P

        // ============ GEMM1: th = tanh(z @ W1 + b1) ============
        uint32_t ah[4], al[4];   // th A-fragments for GEMM2 (this warp's 16 h)
        {
            float dH[2][4], dX[2][4];
            #pragma unroll
            for (int j = 0; j < 2; j++) {
                dH[j][0] = b1f[j][0]; dH[j][1] = b1f[j][1];
                dH[j][2] = b1f[j][0]; dH[j][3] = b1f[j][1];
                dX[j][0] = 0.0f; dX[j][1] = 0.0f; dX[j][2] = 0.0f; dX[j][3] = 0.0f;
            }
            #pragma unroll
            for (int ko = 0; ko < 4; ko++) {
                uint32_t azh[4], azl[4];
                ldm4(zhB + 32*ko, azh);
                ldm4(zlB + 32*ko, azl);
                #pragma unroll
                for (int j = 0; j < 2; j++) {
                    mma16816(dH[j], azh, w1h[j][ko][0], w1h[j][ko][1]);
                    mma16816(dX[j], azl, w1h[j][ko][0], w1h[j][ko][1]);
                    mma16816(dX[j], azh, w1l[j][ko][0], w1l[j][ko][1]);
                }
            }
            float t00 = tanh_fast(dH[0][0] + dX[0][0]);
            float t01 = tanh_fast(dH[0][1] + dX[0][1]);
            float t02 = tanh_fast(dH[0][2] + dX[0][2]);
            float t03 = tanh_fast(dH[0][3] + dX[0][3]);
            float t10 = tanh_fast(dH[1][0] + dX[1][0]);
            float t11 = tanh_fast(dH[1][1] + dX[1][1]);
            float t12 = tanh_fast(dH[1][2] + dX[1][2]);
            float t13 = tanh_fast(dH[1][3] + dX[1][3]);
            split2(t00, t01, ah[0], al[0]);   // a0: rows 0-7, k 0-7
            split2(t02, t03, ah[1], al[1]);   // a1: rows 8-15, k 0-7
            split2(t10, t11, ah[2], al[2]);   // a2: rows 0-7, k 8-15
            split2(t12, t13, ah[3], al[3]);   // a3: rows 8-15, k 8-15
        }

        // ============ GEMM2 (k-split): partials for all 64 l over this k16 ====
        #pragma unroll
        for (int g = 0; g < 2; g++) {
            float D[4][4];
            #pragma unroll
            for (int i = 0; i < 4; i++) {
                D[i][0] = 0.0f; D[i][1] = 0.0f; D[i][2] = 0.0f; D[i][3] = 0.0f;
                int nj = 4*g + i;
                mma16816(D[i], ah, w2h[nj][0], w2h[nj][1]);
                mma16816(D[i], al, w2h[nj][0], w2h[nj][1]);
                mma16816(D[i], ah, w2l[nj][0], w2l[nj][1]);
            }
            #pragma unroll
            for (int i = 0; i < 4; i++) {
                int nj = 4*g + i;
                int l0 = 8*nj + 2*c;
                int s  = 16*mt + hq;
                Pf[pidx(wn, l0,     s)]     = D[i][0];
                Pf[pidx(wn, l0 + 1, s)]     = D[i][1];
                Pf[pidx(wn, l0,     s + 8)] = D[i][2];
                Pf[pidx(wn, l0 + 1, s + 8)] = D[i][3];
            }
        }
        __syncthreads();   // #2: partials ready

        // ============ stage1: reduce k-partials + moments ============
        {
            const int pb = lS*PWD + ((s0 + 8*(lS & 3)) & 31);
            float4 a0 = *(const float4*)&Pf[pb];
            float4 a1 = *(const float4*)&Pf[pb + PBLK];
            float4 a2 = *(const float4*)&Pf[pb + 2*PBLK];
            float4 a3 = *(const float4*)&Pf[pb + 3*PBLK];
            float4 a4 = *(const float4*)&Pf[pb + 4*PBLK];
            float4 a5 = *(const float4*)&Pf[pb + 5*PBLK];
            float4 a6 = *(const float4*)&Pf[pb + 6*PBLK];
            float4 a7 = *(const float4*)&Pf[pb + 7*PBLK];
            float m[4];
            m[0] = ((a0.x+a1.x)+(a2.x+a3.x)) + ((a4.x+a5.x)+(a6.x+a7.x));
            m[1] = ((a0.y+a1.y)+(a2.y+a3.y)) + ((a4.y+a5.y)+(a6.y+a7.y));
            m[2] = ((a0.z+a1.z)+(a2.z+a3.z)) + ((a4.z+a5.z)+(a6.z+a7.z));
            m[3] = ((a0.w+a1.w)+(a2.w+a3.w)) + ((a4.w+a5.w)+(a6.w+a7.w));
            float s1 = 0.0f, s2 = 0.0f;
            #pragma unroll
            for (int i = 0; i < 4; i++) {
                int s = s0 + i;
                float mv = m[i] + zf[s*ZFW + lS] + b2v;
                if (s >= Sn) mv = 0.0f;
                s1 += mv;
                s2 = fmaf(mv, mv, s2);
            }
            sR1[sg*ZFW + lS] = s1;
            sR2[sg*ZFW + lS] = s2;
        }
        __syncthreads();   // #3: moment partials ready

        // -------- filter update (all threads, redundant per l) --------
        float s1 = ((sR1[lq] + sR1[ZFW+lq]) + (sR1[2*ZFW+lq] + sR1[3*ZFW+lq]))
                 + ((sR1[4*ZFW+lq] + sR1[5*ZFW+lq]) + (sR1[6*ZFW+lq] + sR1[7*ZFW+lq]));
        float s2 = ((sR2[lq] + sR2[ZFW+lq]) + (sR2[2*ZFW+lq] + sR2[3*ZFW+lq]))
                 + ((sR2[4*ZFW+lq] + sR2[5*ZFW+lq]) + (sR2[6*ZFW+lq] + sR2[7*ZFW+lq]));
        float mp = s1 * (1.0f/25.0f);
        float Pp = Qd + s2 * (1.0f/25.0f) - mp*mp;
        float Jp = 1.0f / Pp;
        float Jf = Jp + Kv_pf;
        float Pfv = 1.0f / Jf;
        float mf = Pfv * (Jp*mp + kv_pf);
        float spf = sqrtf(Pfv);
        if (tid < 64) {
            out[ZF_SZ + 0*M_SZ + go] = mf;
            out[ZF_SZ + 1*M_SZ + go] = mp;
            out[ZF_SZ + 2*M_SZ + go] = Pfv;
            out[ZF_SZ + 3*M_SZ + go] = Pp;
        }

        // -------- z update + z_f output --------
        #pragma unroll
        for (int i = 0; i < 3; i++) {
            int idx = tid + i*NT, s = idx >> 6;
            float zv = mf + spf * npf[i];
            out[((s*Bn + b)*Tn + t)*Ln + lq] = zv;
            zf[s*ZFW + lq] = zv;
            float zvh = __bfloat162float(__float2bfloat16(zv));
            zh[s*72 + lq] = __float2bfloat16(zv);
            zl[s*72 + lq] = __float2bfloat16(zv - zvh);
        }
        if (tid < 64) {
            float zv = mf + spf * npf[3];
            out[((24*Bn + b)*Tn + t)*Ln + lq] = zv;
            zf[24*ZFW + lq] = zv;
            float zvh = __bfloat162float(__float2bfloat16(zv));
            zh[24*72 + lq] = __float2bfloat16(zv);
            zl[24*72 + lq] = __float2bfloat16(zv - zvh);
        }
    }
}

extern "C" void kernel_launch(void* const* d_in, const int* in_sizes, int n_in,
                              void* d_out, int out_size)
{
    const float* k_in  = (const float*)d_in[0];
    const float* K_in  = (const float*)d_in[1];
    const float* noise = (const float*)d_in[2];
    const float* logQ  = (const float*)d_in[3];
    const float* m0    = (const float*)d_in[4];
    const float* logQ0 = (const float*)d_in[5];
    const float* W1    = (const float*)d_in[6];
    const float* b1    = (const float*)d_in[7];
    const float* W2    = (const float*)d_in[8];
    const float* b2    = (const float*)d_in[9];
    float* out = (float*)d_out;

    cudaFuncSetAttribute(nlf_kernel, cudaFuncAttributeMaxDynamicSharedMemorySize, SMEM_BYTES);
    nlf_kernel<<<Bn, NT, SMEM_BYTES>>>(k_in, K_in, noise, logQ, m0, logQ0,
                                       W1, b1, W2, b2, out);
}

// round 14
// speedup vs baseline: 1.7900x; 1.7900x over previous
#include <cuda_runtime.h>
#include <cuda_fp16.h>
#include <math.h>
#include <stdint.h>

#define Bn 128
#define Tn 256
#define Ln 64
#define Sn 25
#define Hn 128
#define NT 512

#define ZF_SZ  52428800   // 25*128*256*64
#define M_SZ   2097152    // 128*256*64

#define ZW  36    // uint32 words per z fp16 row (64 fp16 = 32 w + 4 pad)
#define TW  68    // uint32 words per th fp16 row (128 fp16 = 64 w + 4 pad)
#define ZFW 68    // float words per exact-z row

__device__ __forceinline__ float tanh_fast(float x) {
    float y;
    asm("tanh.approx.f32 %0, %1;" : "=f"(y) : "f"(x));
    return y;
}
__device__ __forceinline__ uint32_t pack_h2(float a, float b) {
    __half2 h = __floats2half2_rn(a, b);
    return *(uint32_t*)&h;
}
__device__ __forceinline__ void mma16816h(float* d, const uint32_t* a,
                                          uint32_t b0, uint32_t b1) {
    asm volatile(
        "mma.sync.aligned.m16n8k16.row.col.f32.f16.f16.f32 "
        "{%0,%1,%2,%3},{%4,%5,%6,%7},{%8,%9},{%0,%1,%2,%3};"
        : "+f"(d[0]), "+f"(d[1]), "+f"(d[2]), "+f"(d[3])
        : "r"(a[0]), "r"(a[1]), "r"(a[2]), "r"(a[3]), "r"(b0), "r"(b1));
}
__device__ __forceinline__ void ldm4(uint32_t addr, uint32_t* r) {
    asm volatile("ldmatrix.sync.aligned.m8n8.x4.shared.b16 {%0,%1,%2,%3}, [%4];"
        : "=r"(r[0]), "=r"(r[1]), "=r"(r[2]), "=r"(r[3]) : "r"(addr));
}

__global__ __launch_bounds__(NT, 1)
void nlf_kernel(const float* __restrict__ k_in,
                const float* __restrict__ K_in,
                const float* __restrict__ noise,
                const float* __restrict__ logQ,
                const float* __restrict__ m0,
                const float* __restrict__ logQ0,
                const float* __restrict__ W1,
                const float* __restrict__ b1,
                const float* __restrict__ W2,
                const float* __restrict__ b2,
                float* __restrict__ out)
{
    __shared__ uint32_t zH[32*ZW];     // z fp16
    __shared__ uint32_t thH[32*TW];    // tanh fp16
    __shared__ float    zf[32*ZFW];    // exact fp32 z
    __shared__ float    sP1[128], sP2[128];

    const int tid  = threadIdx.x;
    const int b    = blockIdx.x;
    const int w    = tid >> 5;
    const int lane = tid & 31;
    const int lq   = tid & 63;

    const int mt = w & 1;        // s-half m-tile
    const int wn = w >> 1;       // 0..7: GEMM1 h-pair cluster / GEMM2 l-tile
    const int c  = lane & 3;
    const int hq = lane >> 2;

    // ldmatrix per-lane addresses
    const int lrow = mt*16 + (lane & 15);
    const int lcw  = (lane >> 4) * 4;
    const uint32_t zB  = (uint32_t)__cvta_generic_to_shared(zH)  + (lrow*ZW + lcw)*4;
    const uint32_t thB = (uint32_t)__cvta_generic_to_shared(thH) + (lrow*TW + lcw)*4;

    // -------- register-resident fp16 weight B-fragments --------
    uint32_t w1f[2][4][2];
    #pragma unroll
    for (int j = 0; j < 2; j++) {
        int h = 8*(2*wn + j) + hq;
        #pragma unroll
        for (int ko = 0; ko < 4; ko++) {
            int k0 = 16*ko + 2*c;
            w1f[j][ko][0] = pack_h2(W1[(k0+0)*Hn + h], W1[(k0+1)*Hn + h]);
            w1f[j][ko][1] = pack_h2(W1[(k0+8)*Hn + h], W1[(k0+9)*Hn + h]);
        }
    }
    uint32_t w2f[8][2];
    {
        int l2 = 8*wn + hq;
        #pragma unroll
        for (int ko = 0; ko < 8; ko++) {
            int k0 = 16*ko + 2*c;
            w2f[ko][0] = pack_h2(W2[(k0+0)*Ln + l2], W2[(k0+1)*Ln + l2]);
            w2f[ko][1] = pack_h2(W2[(k0+8)*Ln + l2], W2[(k0+9)*Ln + l2]);
        }
    }
    float b1f[2][2];
    #pragma unroll
    for (int j = 0; j < 2; j++) {
        b1f[j][0] = b1[8*(2*wn + j) + 2*c];
        b1f[j][1] = b1[8*(2*wn + j) + 2*c + 1];
    }
    const float b2f0 = b2[8*wn + 2*c];
    const float b2f1 = b2[8*wn + 2*c + 1];
    const float Qd   = log1pf(expf(logQ[lq]));

    __half* zHh = (__half*)zH;     // half stride 72 per row

    // -------- init: zero fp16 arrays, t=0 filter --------
    for (int i = tid; i < 32*ZW; i += NT) zH[i] = 0;
    for (int i = tid; i < 32*TW; i += NT) thH[i] = 0;
    if (tid < 64) {
        int l = tid;
        float P0 = log1pf(expf(logQ0[l]));
        float J0 = 1.0f / P0;
        float h0 = J0 * m0[l];
        int  go  = (b*Tn + 0)*Ln + l;
        float Kv = K_in[go], kv = k_in[go];
        float Jf = J0 + Kv;
        float Pf = 1.0f / Jf;
        float mf = Pf * (h0 + kv);
        out[ZF_SZ + 0*M_SZ + go] = mf;
        out[ZF_SZ + 1*M_SZ + go] = m0[l];
        out[ZF_SZ + 2*M_SZ + go] = Pf;
        out[ZF_SZ + 3*M_SZ + go] = P0;
        sP1[l] = mf;
        sP2[l] = sqrtf(Pf);
    }
    __syncthreads();

    // z update for t = 0
    {
        float mf = sP1[lq], spf = sP2[lq];
        #pragma unroll
        for (int i = 0; i < 3; i++) {
            int idx = tid + i*NT, s = idx >> 6;
            float zv = mf + spf * noise[((0*Sn + s)*Bn + b)*Ln + lq];
            out[((s*Bn + b)*Tn + 0)*Ln + lq] = zv;
            zf[s*ZFW + lq] = zv;
            zHh[s*72 + lq] = __float2half_rn(zv);
        }
        if (tid < 64) {
            float zv = mf + spf * noise[((0*Sn + 24)*Bn + b)*Ln + lq];
            out[((24*Bn + b)*Tn + 0)*Ln + lq] = zv;
            zf[24*ZFW + lq] = zv;
            zHh[24*72 + lq] = __float2half_rn(zv);
        }
    }

    const int rowA = mt*16 + hq;
    const bool storeHi = (mt == 0) || (hq == 0);   // row rowA+8 < 25

    for (int t = 1; t < Tn; t++) {
        // -------- prefetch globals --------
        float npf[4];
        #pragma unroll
        for (int i = 0; i < 3; i++) {
            int idx = tid + i*NT;
            npf[i] = noise[((t*Sn + (idx >> 6))*Bn + b)*Ln + lq];
        }
        npf[3] = (tid < 64) ? noise[((t*Sn + 24)*Bn + b)*Ln + lq] : 0.0f;
        const int go = (b*Tn + t)*Ln + lq;
        const float Kv_pf = K_in[go];
        const float kv_pf = k_in[go];

        __syncthreads();   // #1: z ready

        // ============ GEMM1: th = tanh(z @ W1 + b1), fp16 single-chain ========
        {
            float d[2][4];
            #pragma unroll
            for (int j = 0; j < 2; j++) {
                d[j][0] = b1f[j][0]; d[j][1] = b1f[j][1];
                d[j][2] = b1f[j][0]; d[j][3] = b1f[j][1];
            }
            #pragma unroll
            for (int ko = 0; ko < 4; ko++) {
                uint32_t az[4];
                ldm4(zB + 32*ko, az);
                mma16816h(d[0], az, w1f[0][ko][0], w1f[0][ko][1]);
                mma16816h(d[1], az, w1f[1][ko][0], w1f[1][ko][1]);
            }
            #pragma unroll
            for (int j = 0; j < 2; j++) {
                int nj = 2*wn + j;
                int r0 = rowA*TW + 4*nj + c;
                float t0 = tanh_fast(d[j][0]);
                float t1 = tanh_fast(d[j][1]);
                thH[r0] = pack_h2(t0, t1);
                if (storeHi) {
                    float t2 = tanh_fast(d[j][2]);
                    float t3 = tanh_fast(d[j][3]);
                    thH[r0 + 8*TW] = pack_h2(t2, t3);
                }
            }
        }
        __syncthreads();   // #2: th ready

        // ============ GEMM2: m_th = z + th @ W2 + b2, fused moments ===========
        {
            float e0[4] = {b2f0, b2f1, b2f0, b2f1};
            float e1[4] = {0.0f, 0.0f, 0.0f, 0.0f};
            #pragma unroll
            for (int ko = 0; ko < 4; ko++) {
                uint32_t at[4];
                ldm4(thB + 32*ko, at);
                mma16816h(e0, at, w2f[ko][0], w2f[ko][1]);
            }
            #pragma unroll
            for (int ko = 4; ko < 8; ko++) {
                uint32_t at[4];
                ldm4(thB + 32*ko, at);
                mma16816h(e1, at, w2f[ko][0], w2f[ko][1]);
            }
            int zb = rowA*ZFW + 8*wn + 2*c;
            float m0v = e0[0] + e1[0] + zf[zb];
            float m1v = e0[1] + e1[1] + zf[zb + 1];
            float m2v = e0[2] + e1[2] + zf[zb + 8*ZFW];
            float m3v = e0[3] + e1[3] + zf[zb + 8*ZFW + 1];
            if (mt == 1 && hq > 0) { m2v = 0.0f; m3v = 0.0f; }   // rows >= 25
            float p0 = m0v + m2v, p1 = m1v + m3v;
            float q0 = m0v*m0v + m2v*m2v, q1 = m1v*m1v + m3v*m3v;
            #pragma unroll
            for (int msk = 4; msk <= 16; msk <<= 1) {
                p0 += __shfl_xor_sync(0xffffffffu, p0, msk);
                p1 += __shfl_xor_sync(0xffffffffu, p1, msk);
                q0 += __shfl_xor_sync(0xffffffffu, q0, msk);
                q1 += __shfl_xor_sync(0xffffffffu, q1, msk);
            }
            if (hq == 0) {
                int li = mt*64 + 8*wn + 2*c;
                sP1[li] = p0; sP1[li+1] = p1;
                sP2[li] = q0; sP2[li+1] = q1;
            }
        }
        __syncthreads();   // #3: moment partials ready

        // -------- filter update (all threads, redundant per l) --------
        float s1 = sP1[lq] + sP1[64 + lq];
        float s2 = sP2[lq] + sP2[64 + lq];
        float mp = s1 * (1.0f/25.0f);
        float Pp = Qd + s2 * (1.0f/25.0f) - mp*mp;
        float Jp = 1.0f / Pp;
        float Jf = Jp + Kv_pf;
        float Pf = 1.0f / Jf;
        float mf = Pf * (Jp*mp + kv_pf);
        float spf = sqrtf(Pf);
        if (tid < 64) {
            out[ZF_SZ + 0*M_SZ + go] = mf;
            out[ZF_SZ + 1*M_SZ + go] = mp;
            out[ZF_SZ + 2*M_SZ + go] = Pf;
            out[ZF_SZ + 3*M_SZ + go] = Pp;
        }

        // -------- z update + z_f output --------
        #pragma unroll
        for (int i = 0; i < 3; i++) {
            int idx = tid + i*NT, s = idx >> 6;
            float zv = mf + spf * npf[i];
            out[((s*Bn + b)*Tn + t)*Ln + lq] = zv;
            zf[s*ZFW + lq] = zv;
            zHh[s*72 + lq] = __float2half_rn(zv);
        }
        if (tid < 64) {
            float zv = mf + spf * npf[3];
            out[((24*Bn + b)*Tn + t)*Ln + lq] = zv;
            zf[24*ZFW + lq] = zv;
            zHh[24*72 + lq] = __float2half_rn(zv);
        }
    }
}

extern "C" void kernel_launch(void* const* d_in, const int* in_sizes, int n_in,
                              void* d_out, int out_size)
{
    const float* k_in  = (const float*)d_in[0];
    const float* K_in  = (const float*)d_in[1];
    const float* noise = (const float*)d_in[2];
    const float* logQ  = (const float*)d_in[3];
    const float* m0    = (const float*)d_in[4];
    const float* logQ0 = (const float*)d_in[5];
    const float* W1    = (const float*)d_in[6];
    const float* b1    = (const float*)d_in[7];
    const float* W2    = (const float*)d_in[8];
    const float* b2    = (const float*)d_in[9];
    float* out = (float*)d_out;

    nlf_kernel<<<Bn, NT>>>(k_in, K_in, noise, logQ, m0, logQ0,
                           W1, b1, W2, b2, out);
}